// round 1
// baseline (speedup 1.0000x reference)
#include <cuda_runtime.h>
#include <cuda_fp16.h>
#include <cstdint>

// Problem dims
#define BB   128
#define TT   256
#define FF   64
#define UU   1024
#define G4   4096      // 4*U
#define OUTS 32
#define DH   32
#define KENC 1088      // F + U
#define KRNN 2048      // U + U

#define SMSTRIDE 72    // half elements per smem row (64 + 8 pad)

// ------------------------- device scratch (static, no allocs) ---------------
__device__ __half g_XF16[TT * BB * FF];       // [t][b][f]
__device__ __half g_Wenc[KENC * G4];          // [k][n'], n' = u*4+gate
__device__ __half g_Wcell[KENC * G4];
__device__ __half g_Wrnn[KRNN * G4];
__device__ float  g_benc[G4];
__device__ float  g_bcell[G4];
__device__ float  g_brnn[G4];
__device__ float  g_Hl[BB * UU];
__device__ float  g_Cl[BB * UU];
__device__ float  g_Hr[BB * UU];
__device__ float  g_Cr[BB * UU];
__device__ __half g_H16[2][BB * UU];          // ping-pong h (encoder + lstm_cell)
__device__ __half g_HR16[2][BB * UU];         // ping-pong h (rnn_cell)
__device__ __half g_P16[BB * FF];             // prediction fed back, fp16

// ------------------------- small helpers ------------------------------------
__device__ __forceinline__ void cp16(void* smem, const void* gptr) {
    uint32_t s = (uint32_t)__cvta_generic_to_shared(smem);
    asm volatile("cp.async.cg.shared.global [%0], [%1], 16;" :: "r"(s), "l"(gptr));
}
__device__ __forceinline__ void cp_commit() {
    asm volatile("cp.async.commit_group;");
}
__device__ __forceinline__ void cp_wait0() {
    asm volatile("cp.async.wait_group 0;");
}
__device__ __forceinline__ void ldsm_x4(uint32_t* r, const __half* p) {
    uint32_t a = (uint32_t)__cvta_generic_to_shared(p);
    asm volatile("ldmatrix.sync.aligned.m8n8.x4.shared.b16 {%0,%1,%2,%3}, [%4];"
                 : "=r"(r[0]), "=r"(r[1]), "=r"(r[2]), "=r"(r[3]) : "r"(a));
}
__device__ __forceinline__ void ldsm_x2t(uint32_t* r, const __half* p) {
    uint32_t a = (uint32_t)__cvta_generic_to_shared(p);
    asm volatile("ldmatrix.sync.aligned.m8n8.x2.trans.shared.b16 {%0,%1}, [%2];"
                 : "=r"(r[0]), "=r"(r[1]) : "r"(a));
}
__device__ __forceinline__ void mma16816(float* c, const uint32_t* a, const uint32_t* b) {
    asm volatile(
        "mma.sync.aligned.m16n8k16.row.col.f32.f16.f16.f32 "
        "{%0,%1,%2,%3}, {%4,%5,%6,%7}, {%8,%9}, {%0,%1,%2,%3};"
        : "+f"(c[0]), "+f"(c[1]), "+f"(c[2]), "+f"(c[3])
        : "r"(a[0]), "r"(a[1]), "r"(a[2]), "r"(a[3]), "r"(b[0]), "r"(b[1]));
}
__device__ __forceinline__ float sigmoidf_fast(float x) {
    return 1.0f / (1.0f + __expf(-x));
}

// ------------------------- prep kernels -------------------------------------
// Interleave weight columns to gate-major per unit: dst[k][u*4+gate] = src[k][gate*U+u]
__global__ void prep_w(int sel, const float* __restrict__ W, const float* __restrict__ R,
                       int k0, int K) {
    __half* dst = (sel == 0) ? g_Wenc : (sel == 1) ? g_Wcell : g_Wrnn;
    int idx = blockIdx.x * blockDim.x + threadIdx.x;
    if (idx >= K * G4) return;
    int k = idx >> 12;
    int np = idx & 4095;
    int u = np >> 2, gate = np & 3;
    int col = gate * UU + u;
    float v = (k < k0) ? W[(size_t)k * G4 + col] : R[(size_t)(k - k0) * G4 + col];
    dst[idx] = __float2half_rn(v);
}

__global__ void prep_b(int sel, const float* __restrict__ b) {
    int np = blockIdx.x * blockDim.x + threadIdx.x;
    if (np >= G4) return;
    float* dst = (sel == 0) ? g_benc : (sel == 1) ? g_bcell : g_brnn;
    int u = np >> 2, gate = np & 3;
    dst[np] = b[gate * UU + u];
}

__global__ void conv_x(const float* __restrict__ x) {
    int idx = blockIdx.x * blockDim.x + threadIdx.x;
    if (idx >= TT * BB * FF) return;
    int t = idx / (BB * FF);
    int r = idx % (BB * FF);
    int b = r / FF, f = r % FF;
    g_XF16[idx] = __float2half_rn(x[((size_t)b * TT + t) * FF + f]);
}

__global__ void init_state() {
    int i = blockIdx.x * blockDim.x + threadIdx.x;
    if (i >= BB * UU) return;
    g_Cl[i] = 0.0f;
    g_Hl[i] = 0.0f;
    g_H16[0][i] = __float2half_rn(0.0f);
}

__global__ void copy_state() {
    int i = blockIdx.x * blockDim.x + threadIdx.x;
    if (i >= BB * UU) return;
    float h = g_Hl[i];
    g_Hr[i] = h;
    g_Cr[i] = g_Cl[i];
    g_HR16[0][i] = __float2half_rn(h);
}

// ------------------------- fused GEMM + LSTM-gate step ----------------------
// C[64m x 64z] tile per CTA. grid = (2 m-tiles, 64 n-tiles). 256 threads.
// mode 0: encoder   A=[x_t | h]      W=g_Wenc   state Cl/Hl, H16 ping-pong
// mode 1: lstm_cell A=[pred | hl]    W=g_Wcell  state Cl/Hl, H16 ping-pong
// mode 2: rnn_cell  A=[hl | hr]      W=g_Wrnn   state Cr/Hr, HR16 ping-pong
__global__ void __launch_bounds__(256)
gemm_lstm(int mode, int t, int p0, int p1, int p2) {
    const __half *A0, *A1, *W;
    const float* bias;
    float *Cst, *Hout;
    __half* H16o;
    int K, k0, lda0;

    if (mode == 0) {
        A0 = g_XF16 + (size_t)t * BB * FF; lda0 = FF; k0 = FF;
        A1 = g_H16[p0]; W = g_Wenc; K = KENC; bias = g_benc;
        Cst = g_Cl; Hout = g_Hl; H16o = g_H16[p1];
    } else if (mode == 1) {
        A0 = g_P16; lda0 = FF; k0 = FF;
        A1 = g_H16[p0]; W = g_Wcell; K = KENC; bias = g_bcell;
        Cst = g_Cl; Hout = g_Hl; H16o = g_H16[p1];
    } else {
        A0 = g_H16[p0]; lda0 = UU; k0 = UU;
        A1 = g_HR16[p1]; W = g_Wrnn; K = KRNN; bias = g_brnn;
        Cst = g_Cr; Hout = g_Hr; H16o = g_HR16[p2];
    }

    __shared__ __align__(16) __half sA[2][64 * SMSTRIDE];
    __shared__ __align__(16) __half sB[2][64 * SMSTRIDE];

    const int tid = threadIdx.x;
    const int lane = tid & 31, warp = tid >> 5;
    const int wm = warp >> 2, wn = warp & 3;           // 2 x 4 warp grid
    const int mbase = blockIdx.x * 64;
    const int nbase = blockIdx.y * 64;

    // per-thread load coords (64 rows x 4 chunks of 16 halves)
    const int lr = tid >> 2;
    const int lc = (tid & 3) << 4;

    auto load_chunk = [&](int c, int bf) {
        int kb = c << 6;
        const __half* asrc;
        if (kb < k0) asrc = A0 + (size_t)(mbase + lr) * lda0 + (kb + lc);
        else         asrc = A1 + (size_t)(mbase + lr) * UU + (kb - k0 + lc);
        __half* ad = &sA[bf][lr * SMSTRIDE + lc];
        cp16(ad, asrc);
        cp16(ad + 8, asrc + 8);
        const __half* bsrc = W + (size_t)(kb + lr) * G4 + nbase + lc;
        __half* bd = &sB[bf][lr * SMSTRIDE + lc];
        cp16(bd, bsrc);
        cp16(bd + 8, bsrc + 8);
        cp_commit();
    };

    float acc[2][2][4];
#pragma unroll
    for (int i = 0; i < 2; i++)
#pragma unroll
        for (int j = 0; j < 2; j++)
#pragma unroll
            for (int q = 0; q < 4; q++) acc[i][j][q] = 0.0f;

    const int nchunks = K >> 6;
    load_chunk(0, 0);

    const int lrow = lane & 7;
    const int lsel = lane >> 3;

    for (int c = 0; c < nchunks; c++) {
        cp_wait0();
        __syncthreads();
        if (c + 1 < nchunks) load_chunk(c + 1, (c + 1) & 1);
        int bf = c & 1;

#pragma unroll
        for (int kk = 0; kk < 64; kk += 16) {
            uint32_t af[2][4], bfb[2][2];
#pragma unroll
            for (int mt = 0; mt < 2; mt++) {
                int row = wm * 32 + mt * 16 + lrow + ((lsel & 1) << 3);
                int col = kk + ((lsel >> 1) << 3);
                ldsm_x4(af[mt], &sA[bf][row * SMSTRIDE + col]);
            }
#pragma unroll
            for (int nt = 0; nt < 2; nt++) {
                int row = kk + (lane & 15);
                int col = wn * 16 + nt * 8;
                ldsm_x2t(bfb[nt], &sB[bf][row * SMSTRIDE + col]);
            }
#pragma unroll
            for (int mt = 0; mt < 2; mt++)
#pragma unroll
                for (int nt = 0; nt < 2; nt++)
                    mma16816(acc[mt][nt], af[mt], bfb[nt]);
        }
    }

    // ------- epilogue: dump C to smem, apply LSTM gates -------
    __syncthreads();
    float* sC = (float*)&sA[0][0];  // 64 x 68 floats (17408B <= 18432B)
    const int g = lane >> 2, tg = lane & 3;
#pragma unroll
    for (int mt = 0; mt < 2; mt++)
#pragma unroll
        for (int nt = 0; nt < 2; nt++) {
            int r0 = wm * 32 + mt * 16 + g;
            int c0 = wn * 16 + nt * 8 + 2 * tg;
            sC[r0 * 68 + c0]       = acc[mt][nt][0];
            sC[r0 * 68 + c0 + 1]   = acc[mt][nt][1];
            sC[(r0 + 8) * 68 + c0]     = acc[mt][nt][2];
            sC[(r0 + 8) * 68 + c0 + 1] = acc[mt][nt][3];
        }
    __syncthreads();

    const int ub = nbase >> 2;  // first unit index of this CTA (16 units)
#pragma unroll
    for (int p = tid; p < 64 * 16; p += 256) {
        int bl = p >> 4, ul = p & 15;
        float4 z = *(float4*)&sC[bl * 68 + ul * 4];
        float4 bz = *(const float4*)&bias[nbase + ul * 4];
        float zi = z.x + bz.x, zf = z.y + bz.y, zg = z.z + bz.z, zo = z.w + bz.w;
        int idx = (mbase + bl) * UU + (ub + ul);
        float cold = Cst[idx];
        float iv = sigmoidf_fast(zi);
        float fv = sigmoidf_fast(zf);
        float gv = tanhf(zg);
        float ov = sigmoidf_fast(zo);
        float cn = fv * cold + iv * gv;
        float h = ov * tanhf(cn);
        Cst[idx] = cn;
        Hout[idx] = h;
        H16o[idx] = __float2half_rn(h);
    }
}

// ------------------------- dense head ---------------------------------------
// pred = relu(h @ W1 + b1) @ W2 + b2 ; writes d_out[b][s][:] and g_P16
__global__ void dense_head(int s, const float* __restrict__ W1, const float* __restrict__ b1,
                           const float* __restrict__ W2, const float* __restrict__ b2,
                           float* __restrict__ out) {
    int b = blockIdx.x;
    int tid = threadIdx.x;
    const float* h = (s == 0) ? g_Hl : g_Hr;
    __shared__ float t1[DH];

    int j = tid >> 2, l4 = tid & 3;  // 32 units x 4 threads
    float p = 0.0f;
    for (int k = l4; k < UU; k += 4) p += h[(size_t)b * UU + k] * W1[k * DH + j];
    p += __shfl_xor_sync(0xffffffffu, p, 1);
    p += __shfl_xor_sync(0xffffffffu, p, 2);
    if (l4 == 0) t1[j] = fmaxf(p + b1[j], 0.0f);
    __syncthreads();

    if (tid < FF) {
        float a = b2[tid];
#pragma unroll
        for (int jj = 0; jj < DH; jj++) a += t1[jj] * W2[jj * FF + tid];
        out[((size_t)b * OUTS + s) * FF + tid] = a;
        g_P16[b * FF + tid] = __float2half_rn(a);
    }
}

// ------------------------- launcher -----------------------------------------
extern "C" void kernel_launch(void* const* d_in, const int* in_sizes, int n_in,
                              void* d_out, int out_size) {
    const float* inputs = (const float*)d_in[0];
    const float* Wl = (const float*)d_in[1];
    const float* Rl = (const float*)d_in[2];
    const float* bl = (const float*)d_in[3];
    const float* Wc = (const float*)d_in[4];
    const float* Rc = (const float*)d_in[5];
    const float* bc = (const float*)d_in[6];
    const float* Wr = (const float*)d_in[7];
    const float* Rr = (const float*)d_in[8];
    const float* br = (const float*)d_in[9];
    const float* W1 = (const float*)d_in[10];
    const float* b1 = (const float*)d_in[11];
    const float* W2 = (const float*)d_in[12];
    const float* b2 = (const float*)d_in[13];
    float* out = (float*)d_out;

    prep_w<<<(KENC * G4 + 255) / 256, 256>>>(0, Wl, Rl, FF, KENC);
    prep_w<<<(KENC * G4 + 255) / 256, 256>>>(1, Wc, Rc, FF, KENC);
    prep_w<<<(KRNN * G4 + 255) / 256, 256>>>(2, Wr, Rr, UU, KRNN);
    prep_b<<<(G4 + 255) / 256, 256>>>(0, bl);
    prep_b<<<(G4 + 255) / 256, 256>>>(1, bc);
    prep_b<<<(G4 + 255) / 256, 256>>>(2, br);
    conv_x<<<(TT * BB * FF + 255) / 256, 256>>>(inputs);
    init_state<<<(BB * UU + 255) / 256, 256>>>();

    dim3 grid(2, 64), blk(256);

    // encoder: reads g_H16[t&1], writes g_H16[(t+1)&1]
    for (int t = 0; t < TT; t++)
        gemm_lstm<<<grid, blk>>>(0, t, t & 1, (t + 1) & 1, 0);

    copy_state<<<(BB * UU + 255) / 256, 256>>>();
    dense_head<<<BB, 128>>>(0, W1, b1, W2, b2, out);

    for (int s = 1; s < OUTS; s++) {
        // lstm_cell: reads pred + g_H16[(s+1)&1], writes g_H16[s&1]
        gemm_lstm<<<grid, blk>>>(1, 0, (s + 1) & 1, s & 1, 0);
        // rnn_cell: A=[g_H16[s&1] | g_HR16[(s+1)&1]], writes g_HR16[s&1]
        gemm_lstm<<<grid, blk>>>(2, 0, s & 1, (s + 1) & 1, s & 1);
        dense_head<<<BB, 128>>>(s, W1, b1, W2, b2, out);
    }
}

// round 4
// speedup vs baseline: 1.1708x; 1.1708x over previous
#include <cuda_runtime.h>
#include <cuda_fp16.h>
#include <cstdint>

// Problem dims
#define BB   128
#define TT   256
#define FF   64
#define UU   1024
#define G4   4096      // 4*U
#define OUTS 32
#define DH   32
#define KENC 1088      // F + U
#define KRNN 2048      // U + U
#define NB   128       // grid size (must equal gridDim.x*gridDim.y)

#define SMS 72         // half elements per smem row (64 + 8 pad)

// Smem layout (halves): sW[1088*72] | sA[2][64*72] | sB[2][64*72]
#define SW_HALVES  (KENC * SMS)
#define SAB_HALVES (64 * SMS)
#define SMEM_BYTES ((SW_HALVES + 4 * SAB_HALVES) * 2)

// ------------------------- device scratch (static, no allocs) ---------------
__device__ __half g_XF16[TT * BB * FF];       // [t][b][f]
__device__ __half g_Wenc[KENC * G4];          // [k][n'], n' = u*4+gate
__device__ __half g_Wcell[KENC * G4];
__device__ __half g_Wrnn[KRNN * G4];
__device__ float  g_benc[G4];
__device__ float  g_bcell[G4];
__device__ float  g_brnn[G4];
__device__ float  g_Hl[BB * UU];              // encoder final h (fp32, for dense0)
__device__ float  g_Hr[BB * UU];              // rnn h (fp32, for dense)
__device__ __half g_H16[2][BB * UU];          // ping-pong h (encoder + lstm_cell)
__device__ __half g_HR16[2][BB * UU];         // ping-pong h (rnn_cell)
__device__ __half g_P16[BB * FF];             // prediction fed back, fp16
__device__ unsigned long long g_tick = 0ULL;  // monotone grid-barrier ticket

// ------------------------- small helpers ------------------------------------
__device__ __forceinline__ void cp16(void* smem, const void* gptr) {
    uint32_t s = (uint32_t)__cvta_generic_to_shared(smem);
    asm volatile("cp.async.cg.shared.global [%0], [%1], 16;" :: "r"(s), "l"(gptr));
}
__device__ __forceinline__ void cp_commit() { asm volatile("cp.async.commit_group;"); }
__device__ __forceinline__ void cp_wait0()  { asm volatile("cp.async.wait_group 0;"); }

__device__ __forceinline__ void ldsm_x4(uint32_t* r, const __half* p) {
    uint32_t a = (uint32_t)__cvta_generic_to_shared(p);
    asm volatile("ldmatrix.sync.aligned.m8n8.x4.shared.b16 {%0,%1,%2,%3}, [%4];"
                 : "=r"(r[0]), "=r"(r[1]), "=r"(r[2]), "=r"(r[3]) : "r"(a));
}
__device__ __forceinline__ void ldsm_x2t(uint32_t* r, const __half* p) {
    uint32_t a = (uint32_t)__cvta_generic_to_shared(p);
    asm volatile("ldmatrix.sync.aligned.m8n8.x2.trans.shared.b16 {%0,%1}, [%2];"
                 : "=r"(r[0]), "=r"(r[1]) : "r"(a));
}
__device__ __forceinline__ void mma16816(float* c, const uint32_t* a, const uint32_t* b) {
    asm volatile(
        "mma.sync.aligned.m16n8k16.row.col.f32.f16.f16.f32 "
        "{%0,%1,%2,%3}, {%4,%5,%6,%7}, {%8,%9}, {%0,%1,%2,%3};"
        : "+f"(c[0]), "+f"(c[1]), "+f"(c[2]), "+f"(c[3])
        : "r"(a[0]), "r"(a[1]), "r"(a[2]), "r"(a[3]), "r"(b[0]), "r"(b[1]));
}
__device__ __forceinline__ float sigmoidf_fast(float x) {
    return 1.0f / (1.0f + __expf(-x));
}

// Grid-wide barrier: monotone ticket counter (replay-safe, no reset races).
__device__ __forceinline__ void grid_barrier() {
    __threadfence();          // make this thread's gmem writes visible device-wide
    __syncthreads();
    if (threadIdx.x == 0) {
        unsigned long long v = atomicAdd(&g_tick, 1ULL);
        unsigned long long target = v - (v % NB) + NB;
        while (*(volatile unsigned long long*)&g_tick < target) __nanosleep(32);
        __threadfence();
    }
    __syncthreads();
}

// ------------------------- prep kernels -------------------------------------
__global__ void prep_w(int sel, const float* __restrict__ W, const float* __restrict__ R,
                       int k0, int K) {
    __half* dst = (sel == 0) ? g_Wenc : (sel == 1) ? g_Wcell : g_Wrnn;
    int idx = blockIdx.x * blockDim.x + threadIdx.x;
    if (idx >= K * G4) return;
    int k = idx >> 12;
    int np = idx & 4095;
    int u = np >> 2, gate = np & 3;
    int col = gate * UU + u;
    float v = (k < k0) ? W[(size_t)k * G4 + col] : R[(size_t)(k - k0) * G4 + col];
    dst[idx] = __float2half_rn(v);
}

__global__ void prep_b(int sel, const float* __restrict__ b) {
    int np = blockIdx.x * blockDim.x + threadIdx.x;
    if (np >= G4) return;
    float* dst = (sel == 0) ? g_benc : (sel == 1) ? g_bcell : g_brnn;
    int u = np >> 2, gate = np & 3;
    dst[np] = b[gate * UU + u];
}

__global__ void conv_x(const float* __restrict__ x) {
    int idx = blockIdx.x * blockDim.x + threadIdx.x;
    if (idx >= TT * BB * FF) return;
    int t = idx / (BB * FF);
    int r = idx % (BB * FF);
    int b = r / FF, f = r % FF;
    g_XF16[idx] = __float2half_rn(x[((size_t)b * TT + t) * FF + f]);
}

// ------------------------- persistent-kernel building blocks -----------------
__device__ __forceinline__ void load_W_smem(__half* sW, const __half* gW, int K,
                                            int nbase, int tid) {
    int total = K * 8;  // 8 x 16B per row of 64 halves
    for (int i = tid; i < total; i += 256) {
        int row = i >> 3, c = (i & 7) << 3;
        cp16(&sW[row * SMS + c], gW + (size_t)row * G4 + nbase + c);
    }
    cp_commit();
    cp_wait0();
    __syncthreads();
}

__device__ __forceinline__ void mma_chunk(const __half* sAbuf, const __half* sBrows,
                                          int wm, int wn, int lane,
                                          float acc[2][2][4]) {
    const int lrow = lane & 7, lsel = lane >> 3;
#pragma unroll
    for (int kk = 0; kk < 64; kk += 16) {
        uint32_t af[2][4], bfr[2][2];
#pragma unroll
        for (int mt = 0; mt < 2; mt++) {
            int row = wm * 32 + mt * 16 + lrow + ((lsel & 1) << 3);
            int col = kk + ((lsel >> 1) << 3);
            ldsm_x4(af[mt], &sAbuf[row * SMS + col]);
        }
#pragma unroll
        for (int nt = 0; nt < 2; nt++) {
            int row = kk + (lane & 15);
            int col = wn * 16 + nt * 8;
            ldsm_x2t(bfr[nt], &sBrows[row * SMS + col]);
        }
#pragma unroll
        for (int mt = 0; mt < 2; mt++)
#pragma unroll
            for (int nt = 0; nt < 2; nt++)
                mma16816(acc[mt][nt], af[mt], bfr[nt]);
    }
}

// GEMM over K = nchunks*64. A = [A0 (k0g cols) | A1 (UU-stride cols)].
// B either persistent in smem (sW != nullptr) or streamed from gW via sB ring.
__device__ __forceinline__ void run_gemm(
    const __half* A0, int lda0, int k0g, const __half* A1,
    const __half* sW, const __half* gW,
    __half* sA, __half* sB, int nchunks,
    int tid, int lane, int wm, int wn, int mbase, int nbase,
    float acc[2][2][4])
{
    const int lr = tid >> 2;
    const int lc = (tid & 3) << 4;

    auto issueA = [&](int c, int bf) {
        int kb = c << 6;
        const __half* src = (kb < k0g)
            ? A0 + (size_t)(mbase + lr) * lda0 + kb + lc
            : A1 + (size_t)(mbase + lr) * UU + (kb - k0g) + lc;
        __half* d = sA + bf * SAB_HALVES + lr * SMS + lc;
        cp16(d, src);
        cp16(d + 8, src + 8);
    };
    auto issueB = [&](int c, int bf) {
        int kb = c << 6;
        const __half* src = gW + (size_t)(kb + lr) * G4 + nbase + lc;
        __half* d = sB + bf * SAB_HALVES + lr * SMS + lc;
        cp16(d, src);
        cp16(d + 8, src + 8);
    };

    issueA(0, 0);
    if (!sW) issueB(0, 0);
    cp_commit();

    for (int c = 0; c < nchunks; c++) {
        cp_wait0();
        __syncthreads();
        int bf = c & 1;
        if (c + 1 < nchunks) {
            issueA(c + 1, bf ^ 1);
            if (!sW) issueB(c + 1, bf ^ 1);
            cp_commit();
        }
        const __half* Brows = sW ? (sW + (size_t)(c << 6) * SMS)
                                 : (sB + bf * SAB_HALVES);
        mma_chunk(sA + bf * SAB_HALVES, Brows, wm, wn, lane, acc);
    }
    __syncthreads();  // protect sA before epilogue overlays it as sC
}

// LSTM gate epilogue. c state lives in registers (cst[4]).
__device__ __forceinline__ void epilogue(
    float acc[2][2][4], float* sC, float4 bz, float* cst,
    __half* H16o, __half* H16o2, float* Hf,
    int wm, int wn, int lane, int tid, int mbase, int ub)
{
    const int g = lane >> 2, tg = lane & 3;
#pragma unroll
    for (int mt = 0; mt < 2; mt++)
#pragma unroll
        for (int nt = 0; nt < 2; nt++) {
            int r0 = wm * 32 + mt * 16 + g;
            int c0 = wn * 16 + nt * 8 + 2 * tg;
            sC[r0 * 68 + c0]           = acc[mt][nt][0];
            sC[r0 * 68 + c0 + 1]       = acc[mt][nt][1];
            sC[(r0 + 8) * 68 + c0]     = acc[mt][nt][2];
            sC[(r0 + 8) * 68 + c0 + 1] = acc[mt][nt][3];
        }
    __syncthreads();
    const int ul = tid & 15;
#pragma unroll
    for (int i = 0; i < 4; i++) {
        int bl = (tid >> 4) + i * 16;
        float4 z = *(float4*)&sC[bl * 68 + ul * 4];
        float zi = z.x + bz.x, zf = z.y + bz.y, zg = z.z + bz.z, zo = z.w + bz.w;
        float iv = sigmoidf_fast(zi);
        float fv = sigmoidf_fast(zf);
        float gv = tanhf(zg);
        float ov = sigmoidf_fast(zo);
        float cn = fv * cst[i] + iv * gv;
        float h = ov * tanhf(cn);
        cst[i] = cn;
        int idx = (mbase + bl) * UU + ub + ul;
        __half h16 = __float2half_rn(h);
        H16o[idx] = h16;
        if (H16o2) H16o2[idx] = h16;
        if (Hf) Hf[idx] = h;
    }
}

// Dense head: one batch per CTA. hsrc read via __ldcg (L1-bypass: mutable state).
__device__ __forceinline__ void dense_cta(
    int b, int s, const float* hsrc,
    const float* __restrict__ W1, const float* __restrict__ b1,
    const float* __restrict__ W2, const float* __restrict__ b2,
    float* __restrict__ out, float* sRed, int tid)
{
    int j = tid >> 3, l8 = tid & 7;
    float p = 0.0f;
    const float* hb = hsrc + (size_t)b * UU;
    for (int k = l8; k < UU; k += 8) p += __ldcg(&hb[k]) * W1[k * DH + j];
    p += __shfl_xor_sync(0xffffffffu, p, 1);
    p += __shfl_xor_sync(0xffffffffu, p, 2);
    p += __shfl_xor_sync(0xffffffffu, p, 4);
    if (l8 == 0) sRed[j] = fmaxf(p + b1[j], 0.0f);
    __syncthreads();
    if (tid < FF) {
        float a = b2[tid];
#pragma unroll
        for (int jj = 0; jj < DH; jj++) a += sRed[jj] * W2[jj * FF + tid];
        out[((size_t)b * OUTS + s) * FF + tid] = a;
        g_P16[b * FF + tid] = __float2half_rn(a);
    }
    __syncthreads();
}

__device__ __forceinline__ void zero_acc(float acc[2][2][4]) {
#pragma unroll
    for (int i = 0; i < 2; i++)
#pragma unroll
        for (int j = 0; j < 2; j++)
#pragma unroll
            for (int q = 0; q < 4; q++) acc[i][j][q] = 0.0f;
}

// ------------------------- THE persistent kernel ----------------------------
__global__ void __launch_bounds__(256, 1) rnn_all(
    const float* __restrict__ W1, const float* __restrict__ b1,
    const float* __restrict__ W2, const float* __restrict__ b2,
    float* __restrict__ out)
{
    extern __shared__ __half smem[];
    __half* sW = smem;                         // persistent weight tile
    __half* sA = smem + SW_HALVES;             // A double buffer
    __half* sB = sA + 2 * SAB_HALVES;          // B double buffer (streamed gemms)
    float*  sC = (float*)sA;                   // epilogue overlay (17408B <= 18432B)
    __shared__ float sRed[DH];

    const int tid = threadIdx.x, lane = tid & 31, warp = tid >> 5;
    const int wm = warp >> 2, wn = warp & 3;
    const int mbase = blockIdx.x * 64, nbase = blockIdx.y * 64;
    const int ub = nbase >> 2;
    const int cta = blockIdx.y * 2 + blockIdx.x;
    const int ul = tid & 15;

    float4 bz_enc  = *(const float4*)&g_benc[nbase + ul * 4];
    float4 bz_cell = *(const float4*)&g_bcell[nbase + ul * 4];
    float4 bz_rnn  = *(const float4*)&g_brnn[nbase + ul * 4];

    // prologue: load encoder weights, zero h and c
    load_W_smem(sW, g_Wenc, KENC, nbase, tid);
    float c_l[4] = {0, 0, 0, 0}, c_r[4];
#pragma unroll
    for (int i = 0; i < 4; i++) {
        int bl = (tid >> 4) + i * 16;
        g_H16[0][(mbase + bl) * UU + ub + ul] = __float2half_rn(0.0f);
    }
    grid_barrier();

    float acc[2][2][4];

    // ---------------- encoder: 256 steps ----------------
#pragma unroll 1
    for (int t = 0; t < TT; t++) {
        zero_acc(acc);
        run_gemm(g_XF16 + (size_t)t * BB * FF, FF, FF, g_H16[t & 1],
                 sW, nullptr, sA, sB, KENC >> 6,
                 tid, lane, wm, wn, mbase, nbase, acc);
        bool last = (t == TT - 1);
        epilogue(acc, sC, bz_enc, c_l,
                 g_H16[(t + 1) & 1],
                 last ? g_HR16[0] : nullptr,
                 last ? g_Hl : nullptr,
                 wm, wn, lane, tid, mbase, ub);
        grid_barrier();
    }
#pragma unroll
    for (int i = 0; i < 4; i++) c_r[i] = c_l[i];

    // ---------------- switch to decoder weights ----------------
    load_W_smem(sW, g_Wcell, KENC, nbase, tid);

    // pred0 = dense(encoder h)
    dense_cta(cta, 0, g_Hl, W1, b1, W2, b2, out, sRed, tid);
    grid_barrier();

    // ---------------- decoder: 31 autoregressive steps ----------------
#pragma unroll 1
    for (int s = 1; s < OUTS; s++) {
        // lstm_cell: A = [pred | hl], W = Wcell (smem-resident)
        zero_acc(acc);
        run_gemm(g_P16, FF, FF, g_H16[(s + 1) & 1],
                 sW, nullptr, sA, sB, KENC >> 6,
                 tid, lane, wm, wn, mbase, nbase, acc);
        epilogue(acc, sC, bz_cell, c_l,
                 g_H16[s & 1], nullptr, nullptr,
                 wm, wn, lane, tid, mbase, ub);
        grid_barrier();

        // rnn_cell: A = [hl | hr], W = Wrnn (streamed from L2)
        zero_acc(acc);
        run_gemm(g_H16[s & 1], UU, UU, g_HR16[(s + 1) & 1],
                 nullptr, g_Wrnn, sA, sB, KRNN >> 6,
                 tid, lane, wm, wn, mbase, nbase, acc);
        epilogue(acc, sC, bz_rnn, c_r,
                 g_HR16[s & 1], nullptr, g_Hr,
                 wm, wn, lane, tid, mbase, ub);
        grid_barrier();

        // dense head on hr
        dense_cta(cta, s, g_Hr, W1, b1, W2, b2, out, sRed, tid);
        grid_barrier();
    }
}

// ------------------------- launcher -----------------------------------------
extern "C" void kernel_launch(void* const* d_in, const int* in_sizes, int n_in,
                              void* d_out, int out_size) {
    const float* inputs = (const float*)d_in[0];
    const float* Wl = (const float*)d_in[1];
    const float* Rl = (const float*)d_in[2];
    const float* bl = (const float*)d_in[3];
    const float* Wc = (const float*)d_in[4];
    const float* Rc = (const float*)d_in[5];
    const float* bc = (const float*)d_in[6];
    const float* Wr = (const float*)d_in[7];
    const float* Rr = (const float*)d_in[8];
    const float* br = (const float*)d_in[9];
    const float* W1 = (const float*)d_in[10];
    const float* b1 = (const float*)d_in[11];
    const float* W2 = (const float*)d_in[12];
    const float* b2 = (const float*)d_in[13];
    float* out = (float*)d_out;

    cudaFuncSetAttribute(rnn_all, cudaFuncAttributeMaxDynamicSharedMemorySize,
                         SMEM_BYTES);

    prep_w<<<(KENC * G4 + 255) / 256, 256>>>(0, Wl, Rl, FF, KENC);
    prep_w<<<(KENC * G4 + 255) / 256, 256>>>(1, Wc, Rc, FF, KENC);
    prep_w<<<(KRNN * G4 + 255) / 256, 256>>>(2, Wr, Rr, UU, KRNN);
    prep_b<<<(G4 + 255) / 256, 256>>>(0, bl);
    prep_b<<<(G4 + 255) / 256, 256>>>(1, bc);
    prep_b<<<(G4 + 255) / 256, 256>>>(2, br);
    conv_x<<<(TT * BB * FF + 255) / 256, 256>>>(inputs);

    rnn_all<<<dim3(2, 64), 256, SMEM_BYTES>>>(W1, b1, W2, b2, out);
}

// round 8
// speedup vs baseline: 1.3041x; 1.1139x over previous
#include <cuda_runtime.h>
#include <cuda_fp16.h>
#include <cstdint>

// Problem dims
#define BB   128
#define TT   256
#define FF   64
#define UU   1024
#define G4   4096      // 4*U
#define OUTS 32
#define DH   32
#define KENC 1088      // F + U
#define KRNN 2048      // U + U
#define NB   128       // grid size (must equal gridDim.x*gridDim.y)

#define SMS 72         // half elements per smem row (64 + 8 pad)
#define DEPTH 4        // cp.async pipeline stages

// Smem layout (halves): sW[1088*72] | sA[DEPTH][64*72] | sB[DEPTH][64*72]
#define SW_HALVES  (KENC * SMS)
#define SAB_HALVES (64 * SMS)
#define SMEM_BYTES ((SW_HALVES + 2 * DEPTH * SAB_HALVES) * 2)   // 230400 B

// ------------------------- device scratch (static, no allocs) ---------------
__device__ __half g_XF16[TT * BB * FF];       // [t][b][f]
__device__ __half g_Wenc[KENC * G4];          // [k][n'], n' = u*4+gate
__device__ __half g_Wcell[KENC * G4];
__device__ __half g_Wrnn[KRNN * G4];
__device__ float  g_benc[G4];
__device__ float  g_bcell[G4];
__device__ float  g_brnn[G4];
__device__ float  g_Hl[BB * UU];              // encoder final h (fp32, for dense0)
__device__ float  g_Hr[BB * UU];              // rnn h (fp32, for dense)
__device__ __half g_H16[2][BB * UU];          // ping-pong h (encoder + lstm_cell)
__device__ __half g_HR16[2][BB * UU];         // ping-pong h (rnn_cell)
__device__ __half g_P16[BB * FF];             // prediction fed back, fp16
__device__ unsigned long long g_tick = 0ULL;  // monotone grid-barrier ticket

// ------------------------- small helpers ------------------------------------
__device__ __forceinline__ void cp16(void* smem, const void* gptr) {
    uint32_t s = (uint32_t)__cvta_generic_to_shared(smem);
    asm volatile("cp.async.cg.shared.global [%0], [%1], 16;" :: "r"(s), "l"(gptr));
}
__device__ __forceinline__ void cp_commit() { asm volatile("cp.async.commit_group;"); }
template<int N> __device__ __forceinline__ void cp_wait() {
    asm volatile("cp.async.wait_group %0;" :: "n"(N));
}

__device__ __forceinline__ void ldsm_x4(uint32_t* r, const __half* p) {
    uint32_t a = (uint32_t)__cvta_generic_to_shared(p);
    asm volatile("ldmatrix.sync.aligned.m8n8.x4.shared.b16 {%0,%1,%2,%3}, [%4];"
                 : "=r"(r[0]), "=r"(r[1]), "=r"(r[2]), "=r"(r[3]) : "r"(a));
}
__device__ __forceinline__ void ldsm_x2t(uint32_t* r, const __half* p) {
    uint32_t a = (uint32_t)__cvta_generic_to_shared(p);
    asm volatile("ldmatrix.sync.aligned.m8n8.x2.trans.shared.b16 {%0,%1}, [%2];"
                 : "=r"(r[0]), "=r"(r[1]) : "r"(a));
}
__device__ __forceinline__ void mma16816(float* c, const uint32_t* a, const uint32_t* b) {
    asm volatile(
        "mma.sync.aligned.m16n8k16.row.col.f32.f16.f16.f32 "
        "{%0,%1,%2,%3}, {%4,%5,%6,%7}, {%8,%9}, {%0,%1,%2,%3};"
        : "+f"(c[0]), "+f"(c[1]), "+f"(c[2]), "+f"(c[3])
        : "r"(a[0]), "r"(a[1]), "r"(a[2]), "r"(a[3]), "r"(b[0]), "r"(b[1]));
}
__device__ __forceinline__ float sigmoidf_fast(float x) {
    return 1.0f / (1.0f + __expf(-x));
}

// Grid barrier: monotone ticket. First arrival per launch learns epoch base via
// atomicAdd (g_tick is always a multiple of NB at launch start); later arrivals
// are fire-and-forget red.add + poll. Replay-safe.
__device__ __forceinline__ void grid_barrier(unsigned long long& base, int& cnt) {
    __threadfence();
    __syncthreads();
    if (threadIdx.x == 0) {
        if (cnt == 0) {
            unsigned long long v = atomicAdd(&g_tick, 1ULL);
            base = (v / NB) * NB;
        } else {
            atomicAdd(&g_tick, 1ULL);   // result unused -> RED (no return)
        }
        cnt++;
        unsigned long long target = base + (unsigned long long)cnt * NB;
        while (*(volatile unsigned long long*)&g_tick < target) __nanosleep(16);
        __threadfence();
    }
    __syncthreads();
}

// ------------------------- single merged prep kernel -------------------------
// One launch so the graph is [prep_all, rnn_all] and ncu -s 5 hits rnn_all.
__global__ void prep_all(
    const float* __restrict__ Wl, const float* __restrict__ Rl, const float* __restrict__ bl,
    const float* __restrict__ Wc, const float* __restrict__ Rc, const float* __restrict__ bc,
    const float* __restrict__ Wr, const float* __restrict__ Rr, const float* __restrict__ br,
    const float* __restrict__ x)
{
    size_t idx = (size_t)blockIdx.x * 256 + threadIdx.x;
    const size_t NENC  = (size_t)KENC * G4;   // 4456448
    const size_t NRNN  = (size_t)KRNN * G4;   // 8388608
    const size_t NCONV = (size_t)TT * BB * FF;

    if (idx < NENC) {  // encoder weights
        size_t k = idx >> 12; int np = (int)(idx & 4095);
        int u = np >> 2, gate = np & 3, col = gate * UU + u;
        float v = (k < FF) ? Wl[k * G4 + col] : Rl[(k - FF) * G4 + col];
        g_Wenc[idx] = __float2half_rn(v);
        return;
    }
    idx -= NENC;
    if (idx < NENC) {  // cell weights
        size_t k = idx >> 12; int np = (int)(idx & 4095);
        int u = np >> 2, gate = np & 3, col = gate * UU + u;
        float v = (k < FF) ? Wc[k * G4 + col] : Rc[(k - FF) * G4 + col];
        g_Wcell[idx] = __float2half_rn(v);
        return;
    }
    idx -= NENC;
    if (idx < NRNN) {  // rnn weights
        size_t k = idx >> 12; int np = (int)(idx & 4095);
        int u = np >> 2, gate = np & 3, col = gate * UU + u;
        float v = (k < UU) ? Wr[k * G4 + col] : Rr[(k - UU) * G4 + col];
        g_Wrnn[idx] = __float2half_rn(v);
        return;
    }
    idx -= NRNN;
    if (idx < NCONV) {  // transpose inputs [b][t][f] -> [t][b][f], fp16
        size_t t = idx / (BB * FF);
        int r = (int)(idx % (BB * FF));
        int b = r / FF, f = r % FF;
        g_XF16[idx] = __float2half_rn(x[((size_t)b * TT + t) * FF + f]);
        return;
    }
    idx -= NCONV;
    if (idx < 3 * (size_t)G4) {  // biases
        int sel = (int)(idx >> 12);
        int np = (int)(idx & 4095);
        int u = np >> 2, gate = np & 3;
        const float* b = (sel == 0) ? bl : (sel == 1) ? bc : br;
        float* dst = (sel == 0) ? g_benc : (sel == 1) ? g_bcell : g_brnn;
        dst[np] = b[gate * UU + u];
    }
}

// ------------------------- persistent-kernel building blocks -----------------
__device__ __forceinline__ void load_W_smem(__half* sW, const __half* gW, int K,
                                            int nbase, int tid) {
    int total = K * 8;  // 8 x 16B per row of 64 halves
    for (int i = tid; i < total; i += 256) {
        int row = i >> 3, c = (i & 7) << 3;
        cp16(&sW[row * SMS + c], gW + (size_t)row * G4 + nbase + c);
    }
    cp_commit();
    cp_wait<0>();
    __syncthreads();
}

__device__ __forceinline__ void mma_chunk(const __half* sAbuf, const __half* sBrows,
                                          int wm, int wn, int lane,
                                          float acc[2][2][4]) {
    const int lrow = lane & 7, lsel = lane >> 3;
#pragma unroll
    for (int kk = 0; kk < 64; kk += 16) {
        uint32_t af[2][4], bfr[2][2];
#pragma unroll
        for (int mt = 0; mt < 2; mt++) {
            int row = wm * 32 + mt * 16 + lrow + ((lsel & 1) << 3);
            int col = kk + ((lsel >> 1) << 3);
            ldsm_x4(af[mt], &sAbuf[row * SMS + col]);
        }
#pragma unroll
        for (int nt = 0; nt < 2; nt++) {
            int row = kk + (lane & 15);
            int col = wn * 16 + nt * 8;
            ldsm_x2t(bfr[nt], &sBrows[row * SMS + col]);
        }
#pragma unroll
        for (int mt = 0; mt < 2; mt++)
#pragma unroll
            for (int nt = 0; nt < 2; nt++)
                mma16816(acc[mt][nt], af[mt], bfr[nt]);
    }
}

// Pre-issue stage 0 of A (must be entirely inside A0, i.e. k0g >= 64).
__device__ __forceinline__ void preissue0(const __half* A0, int lda0, __half* sA,
                                          int tid, int mbase) {
    const int lr = tid >> 2, lc = (tid & 3) << 4;
    const __half* src = A0 + (size_t)(mbase + lr) * lda0 + lc;
    __half* d = sA + lr * SMS + lc;
    cp16(d, src);
    cp16(d + 8, src + 8);
    cp_commit();
}

// GEMM over K = nchunks*64. A = [A0 (k0g cols) | A1 (UU-stride cols)].
// B persistent in smem (sW != nullptr) or streamed from gW via sB ring.
// `pre` = stages already issued+committed by caller (each its own group).
__device__ __forceinline__ void run_gemm(
    const __half* A0, int lda0, int k0g, const __half* A1,
    const __half* sW, const __half* gW,
    __half* sA, __half* sB, int nchunks, int pre,
    int tid, int lane, int wm, int wn, int mbase, int nbase,
    float acc[2][2][4])
{
    const int lr = tid >> 2;
    const int lc = (tid & 3) << 4;

    auto issue_st = [&](int st) {
        int bf = st % DEPTH;
        int kb = st << 6;
        const __half* src = (kb < k0g)
            ? A0 + (size_t)(mbase + lr) * lda0 + kb + lc
            : A1 + (size_t)(mbase + lr) * UU + (kb - k0g) + lc;
        __half* d = sA + bf * SAB_HALVES + lr * SMS + lc;
        cp16(d, src);
        cp16(d + 8, src + 8);
        if (gW) {
            const __half* bs = gW + (size_t)(kb + lr) * G4 + nbase + lc;
            __half* bd = sB + bf * SAB_HALVES + lr * SMS + lc;
            cp16(bd, bs);
            cp16(bd + 8, bs + 8);
        }
        cp_commit();
    };

    // prologue: stages [pre, DEPTH-1)
#pragma unroll
    for (int st = 0; st < DEPTH - 1; st++)
        if (st >= pre) issue_st(st);

    for (int c = 0; c < nchunks; c++) {
        int rem = nchunks - 1 - c;
        if (rem >= DEPTH - 2) cp_wait<DEPTH - 2>();
        else if (rem == 1)    cp_wait<1>();
        else                  cp_wait<0>();
        __syncthreads();
        int nxt = c + DEPTH - 1;
        if (nxt < nchunks) issue_st(nxt);
        const __half* Brows = sW ? (sW + (size_t)(c << 6) * SMS)
                                 : (sB + (c % DEPTH) * SAB_HALVES);
        mma_chunk(sA + (c % DEPTH) * SAB_HALVES, Brows, wm, wn, lane, acc);
    }
    __syncthreads();  // protect sA before epilogue overlays it as sC
}

// LSTM gate epilogue. c state lives in registers (cst[4]).
__device__ __forceinline__ void epilogue(
    float acc[2][2][4], float* sC, float4 bz, float* cst,
    __half* H16o, __half* H16o2, float* Hf,
    int wm, int wn, int lane, int tid, int mbase, int ub)
{
    const int g = lane >> 2, tg = lane & 3;
#pragma unroll
    for (int mt = 0; mt < 2; mt++)
#pragma unroll
        for (int nt = 0; nt < 2; nt++) {
            int r0 = wm * 32 + mt * 16 + g;
            int c0 = wn * 16 + nt * 8 + 2 * tg;
            sC[r0 * 68 + c0]           = acc[mt][nt][0];
            sC[r0 * 68 + c0 + 1]       = acc[mt][nt][1];
            sC[(r0 + 8) * 68 + c0]     = acc[mt][nt][2];
            sC[(r0 + 8) * 68 + c0 + 1] = acc[mt][nt][3];
        }
    __syncthreads();
    const int ul = tid & 15;
#pragma unroll
    for (int i = 0; i < 4; i++) {
        int bl = (tid >> 4) + i * 16;
        float4 z = *(float4*)&sC[bl * 68 + ul * 4];
        float zi = z.x + bz.x, zf = z.y + bz.y, zg = z.z + bz.z, zo = z.w + bz.w;
        float iv = sigmoidf_fast(zi);
        float fv = sigmoidf_fast(zf);
        float gv = tanhf(zg);
        float ov = sigmoidf_fast(zo);
        float cn = fv * cst[i] + iv * gv;
        float h = ov * tanhf(cn);
        cst[i] = cn;
        int idx = (mbase + bl) * UU + ub + ul;
        __half h16 = __float2half_rn(h);
        H16o[idx] = h16;
        if (H16o2) H16o2[idx] = h16;
        if (Hf) Hf[idx] = h;
    }
}

// Dense head: one batch per CTA. hsrc read via __ldcg (L1-bypass: mutable state).
__device__ __forceinline__ void dense_cta(
    int b, int s, const float* hsrc,
    const float* __restrict__ W1, const float* __restrict__ b1,
    const float* __restrict__ W2, const float* __restrict__ b2,
    float* __restrict__ out, float* sRed, int tid)
{
    int j = tid >> 3, l8 = tid & 7;
    float p = 0.0f;
    const float* hb = hsrc + (size_t)b * UU;
    for (int k = l8; k < UU; k += 8) p += __ldcg(&hb[k]) * W1[k * DH + j];
    p += __shfl_xor_sync(0xffffffffu, p, 1);
    p += __shfl_xor_sync(0xffffffffu, p, 2);
    p += __shfl_xor_sync(0xffffffffu, p, 4);
    if (l8 == 0) sRed[j] = fmaxf(p + b1[j], 0.0f);
    __syncthreads();
    if (tid < FF) {
        float a = b2[tid];
#pragma unroll
        for (int jj = 0; jj < DH; jj++) a += sRed[jj] * W2[jj * FF + tid];
        out[((size_t)b * OUTS + s) * FF + tid] = a;
        g_P16[b * FF + tid] = __float2half_rn(a);
    }
    __syncthreads();
}

__device__ __forceinline__ void zero_acc(float acc[2][2][4]) {
#pragma unroll
    for (int i = 0; i < 2; i++)
#pragma unroll
        for (int j = 0; j < 2; j++)
#pragma unroll
            for (int q = 0; q < 4; q++) acc[i][j][q] = 0.0f;
}

// ------------------------- THE persistent kernel ----------------------------
__global__ void __launch_bounds__(256, 1) rnn_all(
    const float* __restrict__ W1, const float* __restrict__ b1,
    const float* __restrict__ W2, const float* __restrict__ b2,
    float* __restrict__ out)
{
    extern __shared__ __half smem[];
    __half* sW = smem;                         // persistent weight tile
    __half* sA = smem + SW_HALVES;             // A ring (DEPTH buffers)
    __half* sB = sA + DEPTH * SAB_HALVES;      // B ring (streamed gemms)
    float*  sC = (float*)sA;                   // epilogue overlay (17408B < 18432B)
    __shared__ float sRed[DH];

    const int tid = threadIdx.x, lane = tid & 31, warp = tid >> 5;
    const int wm = warp >> 2, wn = warp & 3;
    const int mbase = blockIdx.x * 64, nbase = blockIdx.y * 64;
    const int ub = nbase >> 2;
    const int cta = blockIdx.y * 2 + blockIdx.x;
    const int ul = tid & 15;

    unsigned long long bar_base = 0ULL;
    int bar_cnt = 0;

    float4 bz_enc  = *(const float4*)&g_benc[nbase + ul * 4];
    float4 bz_cell = *(const float4*)&g_bcell[nbase + ul * 4];
    float4 bz_rnn  = *(const float4*)&g_brnn[nbase + ul * 4];

    // prologue: load encoder weights, zero h and c, pre-issue x_0 chunk
    load_W_smem(sW, g_Wenc, KENC, nbase, tid);
    float c_l[4] = {0, 0, 0, 0}, c_r[4];
#pragma unroll
    for (int i = 0; i < 4; i++) {
        int bl = (tid >> 4) + i * 16;
        g_H16[0][(mbase + bl) * UU + ub + ul] = __float2half_rn(0.0f);
    }
    preissue0(g_XF16, FF, sA, tid, mbase);
    grid_barrier(bar_base, bar_cnt);

    float acc[2][2][4];

    // ---------------- encoder: 256 steps ----------------
#pragma unroll 1
    for (int t = 0; t < TT; t++) {
        zero_acc(acc);
        run_gemm(g_XF16 + (size_t)t * BB * FF, FF, FF, g_H16[t & 1],
                 sW, nullptr, sA, sB, KENC >> 6, /*pre=*/1,
                 tid, lane, wm, wn, mbase, nbase, acc);
        bool last = (t == TT - 1);
        epilogue(acc, sC, bz_enc, c_l,
                 g_H16[(t + 1) & 1],
                 last ? g_HR16[0] : nullptr,
                 last ? g_Hl : nullptr,
                 wm, wn, lane, tid, mbase, ub);
        __syncthreads();                    // sC reads done before buf0 reuse
        if (!last) preissue0(g_XF16 + (size_t)(t + 1) * BB * FF, FF, sA, tid, mbase);
        grid_barrier(bar_base, bar_cnt);
    }
#pragma unroll
    for (int i = 0; i < 4; i++) c_r[i] = c_l[i];

    // ---------------- switch to decoder weights ----------------
    load_W_smem(sW, g_Wcell, KENC, nbase, tid);

    // pred0 = dense(encoder h)
    dense_cta(cta, 0, g_Hl, W1, b1, W2, b2, out, sRed, tid);
    grid_barrier(bar_base, bar_cnt);

    // ---------------- decoder: 31 autoregressive steps ----------------
#pragma unroll 1
    for (int s = 1; s < OUTS; s++) {
        // lstm_cell: A = [pred | hl], W = Wcell (smem-resident)
        zero_acc(acc);
        run_gemm(g_P16, FF, FF, g_H16[(s + 1) & 1],
                 sW, nullptr, sA, sB, KENC >> 6, /*pre=*/0,
                 tid, lane, wm, wn, mbase, nbase, acc);
        epilogue(acc, sC, bz_cell, c_l,
                 g_H16[s & 1], nullptr, nullptr,
                 wm, wn, lane, tid, mbase, ub);
        grid_barrier(bar_base, bar_cnt);

        // rnn_cell: A = [hl | hr], W = Wrnn (streamed from L2)
        zero_acc(acc);
        run_gemm(g_H16[s & 1], UU, UU, g_HR16[(s + 1) & 1],
                 nullptr, g_Wrnn, sA, sB, KRNN >> 6, /*pre=*/0,
                 tid, lane, wm, wn, mbase, nbase, acc);
        epilogue(acc, sC, bz_rnn, c_r,
                 g_HR16[s & 1], nullptr, g_Hr,
                 wm, wn, lane, tid, mbase, ub);
        grid_barrier(bar_base, bar_cnt);

        // dense head on hr
        dense_cta(cta, s, g_Hr, W1, b1, W2, b2, out, sRed, tid);
        grid_barrier(bar_base, bar_cnt);
    }
}

// ------------------------- launcher -----------------------------------------
extern "C" void kernel_launch(void* const* d_in, const int* in_sizes, int n_in,
                              void* d_out, int out_size) {
    const float* inputs = (const float*)d_in[0];
    const float* Wl = (const float*)d_in[1];
    const float* Rl = (const float*)d_in[2];
    const float* bl = (const float*)d_in[3];
    const float* Wc = (const float*)d_in[4];
    const float* Rc = (const float*)d_in[5];
    const float* bc = (const float*)d_in[6];
    const float* Wr = (const float*)d_in[7];
    const float* Rr = (const float*)d_in[8];
    const float* br = (const float*)d_in[9];
    const float* W1 = (const float*)d_in[10];
    const float* b1 = (const float*)d_in[11];
    const float* W2 = (const float*)d_in[12];
    const float* b2 = (const float*)d_in[13];
    float* out = (float*)d_out;

    cudaFuncSetAttribute(rnn_all, cudaFuncAttributeMaxDynamicSharedMemorySize,
                         SMEM_BYTES);

    size_t total = 2 * (size_t)KENC * G4 + (size_t)KRNN * G4
                 + (size_t)TT * BB * FF + 3 * (size_t)G4;
    int blocks = (int)((total + 255) / 256);
    prep_all<<<blocks, 256>>>(Wl, Rl, bl, Wc, Rc, bc, Wr, Rr, br, inputs);

    rnn_all<<<dim3(2, 64), 256, SMEM_BYTES>>>(W1, b1, W2, b2, out);
}

// round 9
// speedup vs baseline: 1.3141x; 1.0076x over previous
#include <cuda_runtime.h>
#include <cuda_fp16.h>
#include <cstdint>

// Problem dims
#define BB   128
#define TT   256
#define FF   64
#define UU   1024
#define G4   4096      // 4*U
#define OUTS 32
#define DH   32
#define KENC 1088      // F + U
#define KRNN 2048      // U + U
#define NB   128       // grid size (must equal gridDim.x*gridDim.y)

#define SMS 72         // half elements per smem row (64 + 8 pad)
#define DEPTH 4        // cp.async pipeline stages

// Smem layout (halves): sW[1088*72] | sA[DEPTH][64*72] | sB[DEPTH][64*72]
#define SW_HALVES  (KENC * SMS)
#define SAB_HALVES (64 * SMS)
#define SMEM_BYTES ((SW_HALVES + 2 * DEPTH * SAB_HALVES) * 2)   // 230400 B

// ------------------------- device scratch (static, no allocs) ---------------
__device__ __half g_XF16[TT * BB * FF];       // [t][b][f]
__device__ __half g_Wenc[KENC * G4];          // [k][n'], n' = u*4+gate
__device__ __half g_Wcell[KENC * G4];
__device__ __half g_Wrnn[KRNN * G4];
__device__ float  g_benc[G4];
__device__ float  g_bcell[G4];
__device__ float  g_brnn[G4];
__device__ float  g_Hl[BB * UU];              // encoder final h (fp32, for dense0)
__device__ float  g_Hr[BB * UU];              // rnn h (fp32, for dense)
__device__ __half g_H16[2][BB * UU];          // ping-pong h (encoder + lstm_cell)
__device__ __half g_HR16[2][BB * UU];         // ping-pong h (rnn_cell)
__device__ __half g_P16[BB * FF];             // prediction fed back, fp16
__device__ unsigned long long g_tick = 0ULL;  // monotone grid-barrier ticket

// ------------------------- small helpers ------------------------------------
__device__ __forceinline__ void cp16(void* smem, const void* gptr) {
    uint32_t s = (uint32_t)__cvta_generic_to_shared(smem);
    asm volatile("cp.async.cg.shared.global [%0], [%1], 16;" :: "r"(s), "l"(gptr));
}
__device__ __forceinline__ void cp_commit() { asm volatile("cp.async.commit_group;"); }
template<int N> __device__ __forceinline__ void cp_wait() {
    asm volatile("cp.async.wait_group %0;" :: "n"(N));
}

__device__ __forceinline__ void ldsm_x4(uint32_t* r, const __half* p) {
    uint32_t a = (uint32_t)__cvta_generic_to_shared(p);
    asm volatile("ldmatrix.sync.aligned.m8n8.x4.shared.b16 {%0,%1,%2,%3}, [%4];"
                 : "=r"(r[0]), "=r"(r[1]), "=r"(r[2]), "=r"(r[3]) : "r"(a));
}
__device__ __forceinline__ void ldsm_x2t(uint32_t* r, const __half* p) {
    uint32_t a = (uint32_t)__cvta_generic_to_shared(p);
    asm volatile("ldmatrix.sync.aligned.m8n8.x2.trans.shared.b16 {%0,%1}, [%2];"
                 : "=r"(r[0]), "=r"(r[1]) : "r"(a));
}
__device__ __forceinline__ void mma16816(float* c, const uint32_t* a, const uint32_t* b) {
    asm volatile(
        "mma.sync.aligned.m16n8k16.row.col.f32.f16.f16.f32 "
        "{%0,%1,%2,%3}, {%4,%5,%6,%7}, {%8,%9}, {%0,%1,%2,%3};"
        : "+f"(c[0]), "+f"(c[1]), "+f"(c[2]), "+f"(c[3])
        : "r"(a[0]), "r"(a[1]), "r"(a[2]), "r"(a[3]), "r"(b[0]), "r"(b[1]));
}
__device__ __forceinline__ float sigmoidf_fast(float x) {
    return 1.0f / (1.0f + __expf(-x));
}

// Grid barrier: monotone ticket. First arrival per launch learns epoch base via
// atomicAdd (g_tick is always a multiple of NB at launch start); later arrivals
// are fire-and-forget red.add + poll. Replay-safe.
__device__ __forceinline__ void grid_barrier(unsigned long long& base, int& cnt) {
    __threadfence();
    __syncthreads();
    if (threadIdx.x == 0) {
        if (cnt == 0) {
            unsigned long long v = atomicAdd(&g_tick, 1ULL);
            base = (v / NB) * NB;
        } else {
            atomicAdd(&g_tick, 1ULL);   // result unused -> RED (no return)
        }
        cnt++;
        unsigned long long target = base + (unsigned long long)cnt * NB;
        while (*(volatile unsigned long long*)&g_tick < target) __nanosleep(16);
        __threadfence();
    }
    __syncthreads();
}

// ------------------------- single merged prep kernel -------------------------
// One launch so the graph is [prep_all, rnn_all] and ncu -s 5 hits rnn_all.
__global__ void prep_all(
    const float* __restrict__ Wl, const float* __restrict__ Rl, const float* __restrict__ bl,
    const float* __restrict__ Wc, const float* __restrict__ Rc, const float* __restrict__ bc,
    const float* __restrict__ Wr, const float* __restrict__ Rr, const float* __restrict__ br,
    const float* __restrict__ x)
{
    size_t idx = (size_t)blockIdx.x * 256 + threadIdx.x;
    const size_t NENC  = (size_t)KENC * G4;   // 4456448
    const size_t NRNN  = (size_t)KRNN * G4;   // 8388608
    const size_t NCONV = (size_t)TT * BB * FF;

    if (idx < NENC) {  // encoder weights
        size_t k = idx >> 12; int np = (int)(idx & 4095);
        int u = np >> 2, gate = np & 3, col = gate * UU + u;
        float v = (k < FF) ? Wl[k * G4 + col] : Rl[(k - FF) * G4 + col];
        g_Wenc[idx] = __float2half_rn(v);
        return;
    }
    idx -= NENC;
    if (idx < NENC) {  // cell weights
        size_t k = idx >> 12; int np = (int)(idx & 4095);
        int u = np >> 2, gate = np & 3, col = gate * UU + u;
        float v = (k < FF) ? Wc[k * G4 + col] : Rc[(k - FF) * G4 + col];
        g_Wcell[idx] = __float2half_rn(v);
        return;
    }
    idx -= NENC;
    if (idx < NRNN) {  // rnn weights
        size_t k = idx >> 12; int np = (int)(idx & 4095);
        int u = np >> 2, gate = np & 3, col = gate * UU + u;
        float v = (k < UU) ? Wr[k * G4 + col] : Rr[(k - UU) * G4 + col];
        g_Wrnn[idx] = __float2half_rn(v);
        return;
    }
    idx -= NRNN;
    if (idx < NCONV) {  // transpose inputs [b][t][f] -> [t][b][f], fp16
        size_t t = idx / (BB * FF);
        int r = (int)(idx % (BB * FF));
        int b = r / FF, f = r % FF;
        g_XF16[idx] = __float2half_rn(x[((size_t)b * TT + t) * FF + f]);
        return;
    }
    idx -= NCONV;
    if (idx < 3 * (size_t)G4) {  // biases
        int sel = (int)(idx >> 12);
        int np = (int)(idx & 4095);
        int u = np >> 2, gate = np & 3;
        const float* b = (sel == 0) ? bl : (sel == 1) ? bc : br;
        float* dst = (sel == 0) ? g_benc : (sel == 1) ? g_bcell : g_brnn;
        dst[np] = b[gate * UU + u];
    }
}

// ------------------------- persistent-kernel building blocks -----------------
__device__ __forceinline__ void load_W_smem(__half* sW, const __half* gW, int K,
                                            int nbase, int tid) {
    int total = K * 8;  // 8 x 16B per row of 64 halves
    for (int i = tid; i < total; i += 256) {
        int row = i >> 3, c = (i & 7) << 3;
        cp16(&sW[row * SMS + c], gW + (size_t)row * G4 + nbase + c);
    }
    cp_commit();
    cp_wait<0>();
    __syncthreads();
}

__device__ __forceinline__ void mma_chunk(const __half* sAbuf, const __half* sBrows,
                                          int wm, int wn, int lane,
                                          float acc[2][2][4]) {
    const int lrow = lane & 7, lsel = lane >> 3;
#pragma unroll
    for (int kk = 0; kk < 64; kk += 16) {
        uint32_t af[2][4], bfr[2][2];
#pragma unroll
        for (int mt = 0; mt < 2; mt++) {
            int row = wm * 32 + mt * 16 + lrow + ((lsel & 1) << 3);
            int col = kk + ((lsel >> 1) << 3);
            ldsm_x4(af[mt], &sAbuf[row * SMS + col]);
        }
#pragma unroll
        for (int nt = 0; nt < 2; nt++) {
            int row = kk + (lane & 15);
            int col = wn * 16 + nt * 8;
            ldsm_x2t(bfr[nt], &sBrows[row * SMS + col]);
        }
#pragma unroll
        for (int mt = 0; mt < 2; mt++)
#pragma unroll
            for (int nt = 0; nt < 2; nt++)
                mma16816(acc[mt][nt], af[mt], bfr[nt]);
    }
}

// Pre-issue stage 0 of A (must be entirely inside A0, i.e. k0g >= 64).
__device__ __forceinline__ void preissue0(const __half* A0, int lda0, __half* sA,
                                          int tid, int mbase) {
    const int lr = tid >> 2, lc = (tid & 3) << 4;
    const __half* src = A0 + (size_t)(mbase + lr) * lda0 + lc;
    __half* d = sA + lr * SMS + lc;
    cp16(d, src);
    cp16(d + 8, src + 8);
    cp_commit();
}

// GEMM over K = nchunks*64. A = [A0 (k0g cols) | A1 (UU-stride cols)].
// B persistent in smem (sW != nullptr) or streamed from gW via sB ring.
// `pre` = stages already issued+committed by caller (each its own group).
__device__ __forceinline__ void run_gemm(
    const __half* A0, int lda0, int k0g, const __half* A1,
    const __half* sW, const __half* gW,
    __half* sA, __half* sB, int nchunks, int pre,
    int tid, int lane, int wm, int wn, int mbase, int nbase,
    float acc[2][2][4])
{
    const int lr = tid >> 2;
    const int lc = (tid & 3) << 4;

    auto issue_st = [&](int st) {
        int bf = st % DEPTH;
        int kb = st << 6;
        const __half* src = (kb < k0g)
            ? A0 + (size_t)(mbase + lr) * lda0 + kb + lc
            : A1 + (size_t)(mbase + lr) * UU + (kb - k0g) + lc;
        __half* d = sA + bf * SAB_HALVES + lr * SMS + lc;
        cp16(d, src);
        cp16(d + 8, src + 8);
        if (gW) {
            const __half* bs = gW + (size_t)(kb + lr) * G4 + nbase + lc;
            __half* bd = sB + bf * SAB_HALVES + lr * SMS + lc;
            cp16(bd, bs);
            cp16(bd + 8, bs + 8);
        }
        cp_commit();
    };

    // prologue: stages [pre, DEPTH-1)
#pragma unroll
    for (int st = 0; st < DEPTH - 1; st++)
        if (st >= pre) issue_st(st);

    for (int c = 0; c < nchunks; c++) {
        int rem = nchunks - 1 - c;
        if (rem >= DEPTH - 2) cp_wait<DEPTH - 2>();
        else if (rem == 1)    cp_wait<1>();
        else                  cp_wait<0>();
        __syncthreads();
        int nxt = c + DEPTH - 1;
        if (nxt < nchunks) issue_st(nxt);
        const __half* Brows = sW ? (sW + (size_t)(c << 6) * SMS)
                                 : (sB + (c % DEPTH) * SAB_HALVES);
        mma_chunk(sA + (c % DEPTH) * SAB_HALVES, Brows, wm, wn, lane, acc);
    }
    __syncthreads();  // protect sA before epilogue overlays it as sC
}

// LSTM gate epilogue. c state lives in registers (cst[4]).
__device__ __forceinline__ void epilogue(
    float acc[2][2][4], float* sC, float4 bz, float* cst,
    __half* H16o, __half* H16o2, float* Hf,
    int wm, int wn, int lane, int tid, int mbase, int ub)
{
    const int g = lane >> 2, tg = lane & 3;
#pragma unroll
    for (int mt = 0; mt < 2; mt++)
#pragma unroll
        for (int nt = 0; nt < 2; nt++) {
            int r0 = wm * 32 + mt * 16 + g;
            int c0 = wn * 16 + nt * 8 + 2 * tg;
            sC[r0 * 68 + c0]           = acc[mt][nt][0];
            sC[r0 * 68 + c0 + 1]       = acc[mt][nt][1];
            sC[(r0 + 8) * 68 + c0]     = acc[mt][nt][2];
            sC[(r0 + 8) * 68 + c0 + 1] = acc[mt][nt][3];
        }
    __syncthreads();
    const int ul = tid & 15;
#pragma unroll
    for (int i = 0; i < 4; i++) {
        int bl = (tid >> 4) + i * 16;
        float4 z = *(float4*)&sC[bl * 68 + ul * 4];
        float zi = z.x + bz.x, zf = z.y + bz.y, zg = z.z + bz.z, zo = z.w + bz.w;
        float iv = sigmoidf_fast(zi);
        float fv = sigmoidf_fast(zf);
        float gv = tanhf(zg);
        float ov = sigmoidf_fast(zo);
        float cn = fv * cst[i] + iv * gv;
        float h = ov * tanhf(cn);
        cst[i] = cn;
        int idx = (mbase + bl) * UU + ub + ul;
        __half h16 = __float2half_rn(h);
        H16o[idx] = h16;
        if (H16o2) H16o2[idx] = h16;
        if (Hf) Hf[idx] = h;
    }
}

// Dense head: one batch per CTA. hsrc read via __ldcg (L1-bypass: mutable state).
__device__ __forceinline__ void dense_cta(
    int b, int s, const float* hsrc,
    const float* __restrict__ W1, const float* __restrict__ b1,
    const float* __restrict__ W2, const float* __restrict__ b2,
    float* __restrict__ out, float* sRed, int tid)
{
    int j = tid >> 3, l8 = tid & 7;
    float p = 0.0f;
    const float* hb = hsrc + (size_t)b * UU;
    for (int k = l8; k < UU; k += 8) p += __ldcg(&hb[k]) * W1[k * DH + j];
    p += __shfl_xor_sync(0xffffffffu, p, 1);
    p += __shfl_xor_sync(0xffffffffu, p, 2);
    p += __shfl_xor_sync(0xffffffffu, p, 4);
    if (l8 == 0) sRed[j] = fmaxf(p + b1[j], 0.0f);
    __syncthreads();
    if (tid < FF) {
        float a = b2[tid];
#pragma unroll
        for (int jj = 0; jj < DH; jj++) a += sRed[jj] * W2[jj * FF + tid];
        out[((size_t)b * OUTS + s) * FF + tid] = a;
        g_P16[b * FF + tid] = __float2half_rn(a);
    }
    __syncthreads();
}

__device__ __forceinline__ void zero_acc(float acc[2][2][4]) {
#pragma unroll
    for (int i = 0; i < 2; i++)
#pragma unroll
        for (int j = 0; j < 2; j++)
#pragma unroll
            for (int q = 0; q < 4; q++) acc[i][j][q] = 0.0f;
}

// ------------------------- THE persistent kernel ----------------------------
__global__ void __launch_bounds__(256, 1) rnn_all(
    const float* __restrict__ W1, const float* __restrict__ b1,
    const float* __restrict__ W2, const float* __restrict__ b2,
    float* __restrict__ out)
{
    extern __shared__ __half smem[];
    __half* sW = smem;                         // persistent weight tile
    __half* sA = smem + SW_HALVES;             // A ring (DEPTH buffers)
    __half* sB = sA + DEPTH * SAB_HALVES;      // B ring (streamed gemms)
    float*  sC = (float*)sA;                   // epilogue overlay (17408B < 18432B)
    __shared__ float sRed[DH];

    const int tid = threadIdx.x, lane = tid & 31, warp = tid >> 5;
    const int wm = warp >> 2, wn = warp & 3;
    const int mbase = blockIdx.x * 64, nbase = blockIdx.y * 64;
    const int ub = nbase >> 2;
    const int cta = blockIdx.y * 2 + blockIdx.x;
    const int ul = tid & 15;

    unsigned long long bar_base = 0ULL;
    int bar_cnt = 0;

    float4 bz_enc  = *(const float4*)&g_benc[nbase + ul * 4];
    float4 bz_cell = *(const float4*)&g_bcell[nbase + ul * 4];
    float4 bz_rnn  = *(const float4*)&g_brnn[nbase + ul * 4];

    // prologue: load encoder weights, zero h and c, pre-issue x_0 chunk
    load_W_smem(sW, g_Wenc, KENC, nbase, tid);
    float c_l[4] = {0, 0, 0, 0}, c_r[4];
#pragma unroll
    for (int i = 0; i < 4; i++) {
        int bl = (tid >> 4) + i * 16;
        g_H16[0][(mbase + bl) * UU + ub + ul] = __float2half_rn(0.0f);
    }
    preissue0(g_XF16, FF, sA, tid, mbase);
    grid_barrier(bar_base, bar_cnt);

    float acc[2][2][4];

    // ---------------- encoder: 256 steps ----------------
#pragma unroll 1
    for (int t = 0; t < TT; t++) {
        zero_acc(acc);
        run_gemm(g_XF16 + (size_t)t * BB * FF, FF, FF, g_H16[t & 1],
                 sW, nullptr, sA, sB, KENC >> 6, /*pre=*/1,
                 tid, lane, wm, wn, mbase, nbase, acc);
        bool last = (t == TT - 1);
        epilogue(acc, sC, bz_enc, c_l,
                 g_H16[(t + 1) & 1],
                 last ? g_HR16[0] : nullptr,
                 last ? g_Hl : nullptr,
                 wm, wn, lane, tid, mbase, ub);
        __syncthreads();                    // sC reads done before buf0 reuse
        if (!last) preissue0(g_XF16 + (size_t)(t + 1) * BB * FF, FF, sA, tid, mbase);
        grid_barrier(bar_base, bar_cnt);
    }
#pragma unroll
    for (int i = 0; i < 4; i++) c_r[i] = c_l[i];

    // ---------------- switch to decoder weights ----------------
    load_W_smem(sW, g_Wcell, KENC, nbase, tid);

    // pred0 = dense(encoder h)
    dense_cta(cta, 0, g_Hl, W1, b1, W2, b2, out, sRed, tid);
    grid_barrier(bar_base, bar_cnt);

    // ---------------- decoder: 31 autoregressive steps ----------------
#pragma unroll 1
    for (int s = 1; s < OUTS; s++) {
        // lstm_cell: A = [pred | hl], W = Wcell (smem-resident)
        zero_acc(acc);
        run_gemm(g_P16, FF, FF, g_H16[(s + 1) & 1],
                 sW, nullptr, sA, sB, KENC >> 6, /*pre=*/0,
                 tid, lane, wm, wn, mbase, nbase, acc);
        epilogue(acc, sC, bz_cell, c_l,
                 g_H16[s & 1], nullptr, nullptr,
                 wm, wn, lane, tid, mbase, ub);
        grid_barrier(bar_base, bar_cnt);

        // rnn_cell: A = [hl | hr], W = Wrnn (streamed from L2)
        zero_acc(acc);
        run_gemm(g_H16[s & 1], UU, UU, g_HR16[(s + 1) & 1],
                 nullptr, g_Wrnn, sA, sB, KRNN >> 6, /*pre=*/0,
                 tid, lane, wm, wn, mbase, nbase, acc);
        epilogue(acc, sC, bz_rnn, c_r,
                 g_HR16[s & 1], nullptr, g_Hr,
                 wm, wn, lane, tid, mbase, ub);
        grid_barrier(bar_base, bar_cnt);

        // dense head on hr
        dense_cta(cta, s, g_Hr, W1, b1, W2, b2, out, sRed, tid);
        grid_barrier(bar_base, bar_cnt);
    }
}

// ------------------------- launcher -----------------------------------------
extern "C" void kernel_launch(void* const* d_in, const int* in_sizes, int n_in,
                              void* d_out, int out_size) {
    const float* inputs = (const float*)d_in[0];
    const float* Wl = (const float*)d_in[1];
    const float* Rl = (const float*)d_in[2];
    const float* bl = (const float*)d_in[3];
    const float* Wc = (const float*)d_in[4];
    const float* Rc = (const float*)d_in[5];
    const float* bc = (const float*)d_in[6];
    const float* Wr = (const float*)d_in[7];
    const float* Rr = (const float*)d_in[8];
    const float* br = (const float*)d_in[9];
    const float* W1 = (const float*)d_in[10];
    const float* b1 = (const float*)d_in[11];
    const float* W2 = (const float*)d_in[12];
    const float* b2 = (const float*)d_in[13];
    float* out = (float*)d_out;

    cudaFuncSetAttribute(rnn_all, cudaFuncAttributeMaxDynamicSharedMemorySize,
                         SMEM_BYTES);

    size_t total = 2 * (size_t)KENC * G4 + (size_t)KRNN * G4
                 + (size_t)TT * BB * FF + 3 * (size_t)G4;
    int blocks = (int)((total + 255) / 256);
    prep_all<<<blocks, 256>>>(Wl, Rl, bl, Wc, Rc, bc, Wr, Rr, br, inputs);

    rnn_all<<<dim3(2, 64), 256, SMEM_BYTES>>>(W1, b1, W2, b2, out);
}

// round 13
// speedup vs baseline: 1.5848x; 1.2060x over previous
#include <cuda_runtime.h>
#include <cuda_fp16.h>
#include <cstdint>

// Problem dims
#define BB   128
#define TT   256
#define FF   64
#define UU   1024
#define G4   4096
#define OUTS 32
#define DH   32
#define KENC 1088      // F + U -> 17 chunks of K=64
#define KRNN 2048      // U + U -> 32 chunks
#define NB   128       // persistent grid size

// Dynamic smem layout (bytes), all tiles 64 rows x 128B, XOR-swizzled
#define SW_OFF 0                       // 17 x 8192 resident W chunks / decoder B ring
#define SA_OFF (17 * 8192)             // 139264: 6 x 8192 A ring (3 per group)
#define DYN_BYTES (SA_OFF + 6 * 8192)  // 188416

#define SWZ(o) ((o) ^ (((o) >> 3) & 0x70))

// ------------------------- device scratch -----------------------------------
__device__ __align__(16) __half g_XF16[(size_t)TT * BB * FF];  // [t][b][f]
__device__ __align__(16) __half g_Wenc[(size_t)KENC * G4];     // [k][n'], n'=u*4+gate
__device__ __align__(16) __half g_Wcell[(size_t)KENC * G4];
__device__ __align__(16) __half g_Wrnn[(size_t)KRNN * G4];
__device__ float g_benc[G4], g_bcell[G4], g_brnn[G4];
__device__ float g_Hl[BB * UU], g_Hr[BB * UU];
__device__ __align__(16) __half g_H16[2][BB * UU];
__device__ __align__(16) __half g_HR16[2][BB * UU];
__device__ __align__(16) __half g_P16[BB * FF];
__device__ unsigned long long g_tick = 0ull;

// ------------------------- PTX helpers --------------------------------------
__device__ __forceinline__ void cp16u(uint32_t s, const void* g) {
    asm volatile("cp.async.cg.shared.global [%0], [%1], 16;" :: "r"(s), "l"(g));
}
__device__ __forceinline__ void cp_commit() { asm volatile("cp.async.commit_group;"); }
template<int N> __device__ __forceinline__ void cp_wait() {
    asm volatile("cp.async.wait_group %0;" :: "n"(N));
}
__device__ __forceinline__ void bar_named(int id) {
    asm volatile("bar.sync %0, 256;" :: "r"(id) : "memory");
}
__device__ __forceinline__ void ldsm_x4(uint32_t* r, uint32_t a) {
    asm volatile("ldmatrix.sync.aligned.m8n8.x4.shared.b16 {%0,%1,%2,%3}, [%4];"
                 : "=r"(r[0]), "=r"(r[1]), "=r"(r[2]), "=r"(r[3]) : "r"(a));
}
__device__ __forceinline__ void ldsm_x2t(uint32_t* r, uint32_t a) {
    asm volatile("ldmatrix.sync.aligned.m8n8.x2.trans.shared.b16 {%0,%1}, [%2];"
                 : "=r"(r[0]), "=r"(r[1]) : "r"(a));
}
__device__ __forceinline__ void mma16816(float* c, const uint32_t* a, const uint32_t* b) {
    asm volatile(
        "mma.sync.aligned.m16n8k16.row.col.f32.f16.f16.f32 "
        "{%0,%1,%2,%3}, {%4,%5,%6,%7}, {%8,%9}, {%0,%1,%2,%3};"
        : "+f"(c[0]), "+f"(c[1]), "+f"(c[2]), "+f"(c[3])
        : "r"(a[0]), "r"(a[1]), "r"(a[2]), "r"(a[3]), "r"(b[0]), "r"(b[1]));
}
__device__ __forceinline__ float sigmoidf_fast(float x) {
    return 1.0f / (1.0f + __expf(-x));
}

// Grid barrier: monotone ticket (replay-safe).
__device__ __forceinline__ void grid_barrier(unsigned long long& base, int& cnt) {
    __threadfence();
    __syncthreads();
    if (threadIdx.x == 0) {
        if (cnt == 0) {
            unsigned long long v = atomicAdd(&g_tick, 1ull);
            base = (v / NB) * NB;
        } else {
            atomicAdd(&g_tick, 1ull);
        }
        cnt++;
        unsigned long long target = base + (unsigned long long)cnt * NB;
        while (*(volatile unsigned long long*)&g_tick < target) __nanosleep(16);
        __threadfence();
    }
    __syncthreads();
}

// ------------------------- merged prep kernel --------------------------------
__global__ void prep_all(
    const float* __restrict__ Wl, const float* __restrict__ Rl, const float* __restrict__ bl,
    const float* __restrict__ Wc, const float* __restrict__ Rc, const float* __restrict__ bc,
    const float* __restrict__ Wr, const float* __restrict__ Rr, const float* __restrict__ br,
    const float* __restrict__ x)
{
    size_t idx = (size_t)blockIdx.x * 256 + threadIdx.x;
    const size_t NENC  = (size_t)KENC * G4;
    const size_t NRNN  = (size_t)KRNN * G4;
    const size_t NCONV = (size_t)TT * BB * FF;

    if (idx < NENC) {
        size_t k = idx >> 12; int np = (int)(idx & 4095);
        int u = np >> 2, gate = np & 3, col = gate * UU + u;
        float v = (k < FF) ? Wl[k * G4 + col] : Rl[(k - FF) * G4 + col];
        g_Wenc[idx] = __float2half_rn(v);
        return;
    }
    idx -= NENC;
    if (idx < NENC) {
        size_t k = idx >> 12; int np = (int)(idx & 4095);
        int u = np >> 2, gate = np & 3, col = gate * UU + u;
        float v = (k < FF) ? Wc[k * G4 + col] : Rc[(k - FF) * G4 + col];
        g_Wcell[idx] = __float2half_rn(v);
        return;
    }
    idx -= NENC;
    if (idx < NRNN) {
        size_t k = idx >> 12; int np = (int)(idx & 4095);
        int u = np >> 2, gate = np & 3, col = gate * UU + u;
        float v = (k < UU) ? Wr[k * G4 + col] : Rr[(k - UU) * G4 + col];
        g_Wrnn[idx] = __float2half_rn(v);
        return;
    }
    idx -= NRNN;
    if (idx < NCONV) {
        size_t t = idx / (BB * FF);
        int r = (int)(idx % (BB * FF));
        int b = r / FF, f = r % FF;
        g_XF16[idx] = __float2half_rn(x[((size_t)b * TT + t) * FF + f]);
        return;
    }
    idx -= NCONV;
    if (idx < 3 * (size_t)G4) {
        int sel = (int)(idx >> 12), np = (int)(idx & 4095);
        int u = np >> 2, gate = np & 3;
        const float* b = (sel == 0) ? bl : (sel == 1) ? bc : br;
        float* dst = (sel == 0) ? g_benc : (sel == 1) ? g_bcell : g_brnn;
        dst[np] = b[gate * UU + u];
    }
}

// ------------------------- GEMM core (per-group) -----------------------------
__device__ __forceinline__ void mma_chunk(uint32_t bufA, uint32_t bufB,
                                          const uint32_t* offA, const uint32_t* offB,
                                          float acc[2][2][4]) {
#pragma unroll
    for (int kk = 0; kk < 4; kk++) {
        uint32_t af[2][4], bfr[2][2];
#pragma unroll
        for (int mt = 0; mt < 2; mt++) ldsm_x4(af[mt], bufA + offA[kk * 2 + mt]);
#pragma unroll
        for (int nt = 0; nt < 2; nt++) ldsm_x2t(bfr[nt], bufB + offB[kk * 2 + nt]);
#pragma unroll
        for (int mt = 0; mt < 2; mt++)
#pragma unroll
            for (int nt = 0; nt < 2; nt++)
                mma16816(acc[mt][nt], af[mt], bfr[nt]);
    }
}

// One group's GEMM over chunks [cg0, cg0+nchg). A = [A0 (k0g cols) | A1 (UU-stride)].
// B resident (gB==null): chunk c at su + c*8192. Else streamed into sW-region ring.
__device__ __forceinline__ void run_gemm(
    uint32_t su, int g, int tg, int lr, uint32_t o1, uint32_t o2,
    int cg0, int nchg,
    const __half* A0, int lda0, int k0g, const __half* A1,
    const __half* gB, int nbase, int mbase,
    const uint32_t* offA, const uint32_t* offB, float acc[2][2][4],
    int pre)
{
    const int hb = (int)( ( (uint32_t)tg & 3u) << 4 );  // half-col base (bc/2)
    auto issue = [&](int c) {
        int s = (c - cg0) % 3;
        uint32_t bufA = su + SA_OFF + (uint32_t)(g * 3 + s) * 8192;
        int kg = (c << 6) + hb;
        const __half* srcA = (kg < k0g)
            ? A0 + (size_t)(mbase + lr) * lda0 + kg
            : A1 + (size_t)(mbase + lr) * UU + (kg - k0g);
        cp16u(bufA + o1, srcA);
        cp16u(bufA + o2, srcA + 8);
        if (gB) {
            uint32_t bufB = su + (uint32_t)(g * 3 + s) * 8192;
            const __half* srcB = gB + (size_t)((c << 6) + lr) * G4 + nbase + hb;
            cp16u(bufB + o1, srcB);
            cp16u(bufB + o2, srcB + 8);
        }
        cp_commit();
    };

    if (!pre) issue(cg0);
    issue(cg0 + 1);

    const int cend = cg0 + nchg;
    for (int c = cg0; c < cend; c++) {
        if (c < cend - 1) cp_wait<1>();
        else              cp_wait<0>();
        bar_named(1 + g);
        if (c + 2 < cend) issue(c + 2);
        int s = (c - cg0) % 3;
        uint32_t bufA = su + SA_OFF + (uint32_t)(g * 3 + s) * 8192;
        uint32_t bufB = gB ? (su + (uint32_t)(g * 3 + s) * 8192)
                           : (su + (uint32_t)c * 8192);
        mma_chunk(bufA, bufB, offA, offB, acc);
    }
}

// ------------------------- epilogue ------------------------------------------
__device__ __forceinline__ void epilogue(
    char* smem, float acc[2][2][4], const float* sBias, float* cst,
    __half* H16o, __half* H16o2, float* Hf,
    int g, int wm, int wn, int lane, int tid, int mbase, int ub)
{
    bar_named(1 + g);   // group done reading its ring buffers
    float* sCg = (float*)(smem + SA_OFF + g * 24576);
    const int g2 = lane >> 2, t4 = lane & 3;
#pragma unroll
    for (int mt = 0; mt < 2; mt++)
#pragma unroll
        for (int nt = 0; nt < 2; nt++) {
            int r0 = wm * 32 + mt * 16 + g2;
            int c0 = wn * 16 + nt * 8 + 2 * t4;
            sCg[r0 * 68 + c0]           = acc[mt][nt][0];
            sCg[r0 * 68 + c0 + 1]       = acc[mt][nt][1];
            sCg[(r0 + 8) * 68 + c0]     = acc[mt][nt][2];
            sCg[(r0 + 8) * 68 + c0 + 1] = acc[mt][nt][3];
        }
    __syncthreads();
    const float* sC0 = (const float*)(smem + SA_OFF);
    const float* sC1 = (const float*)(smem + SA_OFF + 24576);
    const float4* b4 = (const float4*)sBias;
#pragma unroll
    for (int i = 0; i < 2; i++) {
        int p = tid + (i << 9);
        int bl = p >> 4, ul = p & 15;
        float4 z0 = *(const float4*)&sC0[bl * 68 + ul * 4];
        float4 z1 = *(const float4*)&sC1[bl * 68 + ul * 4];
        float4 bz = b4[ul];
        float zi = z0.x + z1.x + bz.x;
        float zf = z0.y + z1.y + bz.y;
        float zg = z0.z + z1.z + bz.z;
        float zo = z0.w + z1.w + bz.w;
        float cn = sigmoidf_fast(zf) * cst[i] + sigmoidf_fast(zi) * tanhf(zg);
        float h = sigmoidf_fast(zo) * tanhf(cn);
        cst[i] = cn;
        int idx = (mbase + bl) * UU + ub + ul;
        __half h16 = __float2half_rn(h);
        H16o[idx] = h16;
        if (H16o2) H16o2[idx] = h16;
        if (Hf) Hf[idx] = h;
    }
    __syncthreads();    // gates done reading sC before rings are reused
}

// Dense head for batch row b (512 threads).
__device__ __forceinline__ void dense_cta(
    int b, int s, const float* hsrc,
    const float* __restrict__ W1, const float* __restrict__ b1,
    const float* __restrict__ W2, const float* __restrict__ b2,
    float* __restrict__ out, float* sRed, int tid)
{
    int j = tid >> 4, l16 = tid & 15;
    float p = 0.0f;
    const float* hb = hsrc + (size_t)b * UU;
    for (int k = l16; k < UU; k += 16) p += __ldcg(&hb[k]) * W1[k * DH + j];
    p += __shfl_xor_sync(0xffffffffu, p, 1);
    p += __shfl_xor_sync(0xffffffffu, p, 2);
    p += __shfl_xor_sync(0xffffffffu, p, 4);
    p += __shfl_xor_sync(0xffffffffu, p, 8);
    if (l16 == 0) sRed[j] = fmaxf(p + b1[j], 0.0f);
    __syncthreads();
    if (tid < FF) {
        float a = b2[tid];
#pragma unroll
        for (int jj = 0; jj < DH; jj++) a += sRed[jj] * W2[jj * FF + tid];
        out[((size_t)b * OUTS + s) * FF + tid] = a;
        g_P16[b * FF + tid] = __float2half_rn(a);
    }
    __syncthreads();
}

__device__ __forceinline__ void zero_acc(float acc[2][2][4]) {
#pragma unroll
    for (int i = 0; i < 2; i++)
#pragma unroll
        for (int j = 0; j < 2; j++)
#pragma unroll
            for (int q = 0; q < 4; q++) acc[i][j][q] = 0.0f;
}

// ------------------------- THE persistent kernel ----------------------------
__global__ void __launch_bounds__(512, 1) rnn_all(
    const float* __restrict__ W1, const float* __restrict__ b1,
    const float* __restrict__ W2, const float* __restrict__ b2,
    float* __restrict__ out)
{
    extern __shared__ char smem[];
    uint32_t su;
    asm("{ .reg .u64 t; cvta.to.shared.u64 t, %1; cvt.u32.u64 %0, t; }"
        : "=r"(su) : "l"(smem));
    __shared__ float sBias[192];
    __shared__ float sRed[DH];

    const int tid = threadIdx.x, lane = tid & 31, warp = tid >> 5;
    const int g = warp >> 3;                 // k-split group 0/1
    const int wg = warp & 7, wm = wg >> 2, wn = wg & 3;
    const int cta = blockIdx.x;
    const int mbase = (cta & 1) * 64, nbase = (cta >> 1) * 64;
    const int ub = nbase >> 2;
    const int tg = tid & 255;                // thread id within group
    const int lr = tg >> 2;                  // load row 0..63
    const uint32_t bcb = (tg & 3) * 32;      // load byte col
    const uint32_t o1 = SWZ(lr * 128 + bcb);
    const uint32_t o2 = SWZ(lr * 128 + bcb + 16);

    // precomputed swizzled ldsm offsets
    uint32_t offA[8], offB[8];
    {
        const int lrow = lane & 7, lsel = lane >> 3;
#pragma unroll
        for (int kk = 0; kk < 4; kk++) {
#pragma unroll
            for (int mt = 0; mt < 2; mt++) {
                int row = wm * 32 + mt * 16 + lrow + ((lsel & 1) << 3);
                offA[kk * 2 + mt] = SWZ((uint32_t)(row * 128 + kk * 32 + ((lsel >> 1) << 4)));
            }
#pragma unroll
            for (int nt = 0; nt < 2; nt++) {
                int row = kk * 16 + (lane & 15);
                offB[kk * 2 + nt] = SWZ((uint32_t)(row * 128 + wn * 32 + nt * 16));
            }
        }
    }

    unsigned long long bar_base = 0ull;
    int bar_cnt = 0;

    if (tid < 64) {
        sBias[tid]       = g_benc[nbase + tid];
        sBias[64 + tid]  = g_bcell[nbase + tid];
        sBias[128 + tid] = g_brnn[nbase + tid];
    }
    // zero h0 slice
    if (tid < 128) {
        uint4 z = {0, 0, 0, 0};
        ((uint4*)g_H16[0])[cta * 128 + tid] = z;
    }
    // resident encoder weights: 17 chunks x 64 rows x 8 units
    for (int i = tid; i < 17 * 512; i += 512) {
        int c = i >> 9, r = (i >> 3) & 63, u = i & 7;
        cp16u(su + (uint32_t)c * 8192 + SWZ((uint32_t)(r * 128 + u * 16)),
              g_Wenc + (size_t)(c * 64 + r) * G4 + nbase + u * 8);
    }
    cp_commit();
    cp_wait<0>();
    __syncthreads();

    // pre-issue x_0 chunk (group 0, stage 0)
    if (g == 0) {
        const __half* src = g_XF16 + (size_t)(mbase + lr) * FF + (bcb >> 1);
        cp16u(su + SA_OFF + o1, src);
        cp16u(su + SA_OFF + o2, src + 8);
        cp_commit();
    }

    float cl[2] = {0, 0}, cr[2];
    grid_barrier(bar_base, bar_cnt);

    float acc[2][2][4];
    const int cg0e = g ? 9 : 0, nchge = g ? 8 : 9;   // enc/lstm split of 17
    const int cg0r = g ? 16 : 0;                      // rnn split of 32

    // ---------------- encoder: 256 steps ----------------
#pragma unroll 1
    for (int t = 0; t < TT; t++) {
        zero_acc(acc);
        run_gemm(su, g, tg, lr, o1, o2, cg0e, nchge,
                 g_XF16 + (size_t)t * BB * FF, FF, FF, g_H16[t & 1],
                 nullptr, nbase, mbase, offA, offB, acc, (g == 0) ? 1 : 0);
        bool last = (t == TT - 1);
        epilogue(smem, acc, sBias, cl,
                 g_H16[(t + 1) & 1],
                 last ? g_HR16[0] : nullptr,
                 last ? g_Hl : nullptr,
                 g, wm, wn, lane, tid, mbase, ub);
        if (!last && g == 0) {
            const __half* src = g_XF16 + (size_t)(t + 1) * BB * FF
                              + (size_t)(mbase + lr) * FF + (bcb >> 1);
            cp16u(su + SA_OFF + o1, src);
            cp16u(su + SA_OFF + o2, src + 8);
            cp_commit();
        }
        grid_barrier(bar_base, bar_cnt);
    }
    cr[0] = cl[0]; cr[1] = cl[1];

    // pred0 = dense(encoder h)
    dense_cta(cta, 0, g_Hl, W1, b1, W2, b2, out, sRed, tid);
    grid_barrier(bar_base, bar_cnt);

    // ---------------- decoder: 31 steps (weights streamed, sW region = B ring)
#pragma unroll 1
    for (int s = 1; s < OUTS; s++) {
        // lstm_cell: A = [pred | hl], B = Wcell streamed
        zero_acc(acc);
        run_gemm(su, g, tg, lr, o1, o2, cg0e, nchge,
                 g_P16, FF, FF, g_H16[(s + 1) & 1],
                 g_Wcell, nbase, mbase, offA, offB, acc, 0);
        epilogue(smem, acc, sBias + 64, cl,
                 g_H16[s & 1], nullptr, nullptr,
                 g, wm, wn, lane, tid, mbase, ub);
        grid_barrier(bar_base, bar_cnt);

        // rnn_cell: A = [hl | hr], B = Wrnn streamed
        zero_acc(acc);
        run_gemm(su, g, tg, lr, o1, o2, cg0r, 16,
                 g_H16[s & 1], UU, UU, g_HR16[(s + 1) & 1],
                 g_Wrnn, nbase, mbase, offA, offB, acc, 0);
        epilogue(smem, acc, sBias + 128, cr,
                 g_HR16[s & 1], nullptr, g_Hr,
                 g, wm, wn, lane, tid, mbase, ub);
        grid_barrier(bar_base, bar_cnt);

        dense_cta(cta, s, g_Hr, W1, b1, W2, b2, out, sRed, tid);
        grid_barrier(bar_base, bar_cnt);
    }
}

// ------------------------- launcher -----------------------------------------
extern "C" void kernel_launch(void* const* d_in, const int* in_sizes, int n_in,
                              void* d_out, int out_size) {
    const float* inputs = (const float*)d_in[0];
    const float* Wl = (const float*)d_in[1];
    const float* Rl = (const float*)d_in[2];
    const float* bl = (const float*)d_in[3];
    const float* Wc = (const float*)d_in[4];
    const float* Rc = (const float*)d_in[5];
    const float* bc = (const float*)d_in[6];
    const float* Wr = (const float*)d_in[7];
    const float* Rr = (const float*)d_in[8];
    const float* br = (const float*)d_in[9];
    const float* W1 = (const float*)d_in[10];
    const float* b1 = (const float*)d_in[11];
    const float* W2 = (const float*)d_in[12];
    const float* b2 = (const float*)d_in[13];
    float* out = (float*)d_out;

    cudaFuncSetAttribute(rnn_all, cudaFuncAttributeMaxDynamicSharedMemorySize,
                         DYN_BYTES);

    size_t total = 2 * (size_t)KENC * G4 + (size_t)KRNN * G4
                 + (size_t)TT * BB * FF + 3 * (size_t)G4;
    prep_all<<<(int)((total + 255) / 256), 256>>>(Wl, Rl, bl, Wc, Rc, bc,
                                                  Wr, Rr, br, inputs);

    rnn_all<<<NB, 512, DYN_BYTES>>>(W1, b1, W2, b2, out);
}